// round 2
// baseline (speedup 1.0000x reference)
#include <cuda_runtime.h>
#include <cuda_bf16.h>
#include <math_constants.h>

// ---------------------------------------------------------------------------
// VQ-VAE quantize — BIT-EXACT emulation of the JAX/XLA-CPU reference numerics.
//
//   d[n,e] = fl( fl(A_n + B_e) - fl(2 * M_ne) )      (all fp32, exact assoc)
//     A_n  = sequential fp32 sum over k of fl(z_nk^2)        (k ascending)
//     B_e  = sequential fp32 sum over k of fl(cb_ek^2)       (k ascending)
//     M_ne = sequential fp32 FMA chain over k: fmaf(z,cb,acc), acc0=0
//   idx[n] = argmin_e d[n,e]  (first index wins ties — grid-quantized ties
//            are COMMON because ulp(256)=3e-5 >> fp32 noise)
//   z_q_out[b,c,h,w] = codebook[idx[n], c]
//   loss   = 1.25 * sum_n d_min[n] / 8388608   (double accum; err ~2e-7)
// Output (f32): [ z_q_out : 8388608 ][ loss : 1 ][ idx : 32768 ]
// ---------------------------------------------------------------------------

#define N_VEC   32768
#define C_DIM   256
#define N_EMB   1024
#define Z_ELEMS 8388608
#define LOSS_OFF 8388608
#define IDX_OFF  8388609

__device__ float  g_e2[N_EMB];     // B_e = ||e||^2, exact reference order
__device__ float  g_rowA[N_VEC];   // A_n = ||z_n||^2, exact reference order
__device__ int    g_idx[N_VEC];
__device__ double g_loss_sum;

// ---------------------------------------------------------------------------
// k_prep: B_e per codebook row, scalar sequential fp32 (k ascending).
// 1024 threads total; also zero the loss accumulator.
// ---------------------------------------------------------------------------
__global__ void k_prep(const float* __restrict__ cb) {
    int e = blockIdx.x * blockDim.x + threadIdx.x;
    if (e == 0) g_loss_sum = 0.0;
    if (e >= N_EMB) return;
    const float* r = cb + e * C_DIM;
    float s = 0.f;
    for (int k = 0; k < C_DIM; ++k) {
        float v = r[k];
        s = __fadd_rn(s, __fmul_rn(v, v));   // round product, then add: matches zf*zf -> sum
    }
    g_e2[e] = s;
}

// ---------------------------------------------------------------------------
// k_rowA: A_n per z vector, scalar sequential fp32 (k ascending).
// One thread per n; zf[n,k] = z[b*C*4096 + k*4096 + hw]. Coalesced across n.
// ---------------------------------------------------------------------------
__global__ void k_rowA(const float* __restrict__ z) {
    int n  = blockIdx.x * blockDim.x + threadIdx.x;   // 0..32767
    int b  = n >> 12;
    int hw = n & 4095;
    const float* base = z + ((long)b << 20) + hw;     // + k*4096
    float s = 0.f;
    #pragma unroll 8
    for (int k = 0; k < C_DIM; ++k) {
        float v = base[(long)k << 12];
        s = __fadd_rn(s, __fmul_rn(v, v));
    }
    g_rowA[n] = s;
}

// ---------------------------------------------------------------------------
// k_argmin: distance GEMM with the exact reference fp32 chain + fused argmin.
// Block = 256 threads handles TN=64 consecutive n (one (b,h), w=0..63).
// z tile [256c][64n] resident in smem; codebook streamed in k-chunks of 16
// over e-tiles of 64. Thread (tx,ty): 4 n x 4 e; each (n,e) pair is ONE
// fp32 FMA chain over k = 0..255 ascending (never split/reassociated).
// ---------------------------------------------------------------------------
#define TN 64
#define TE 64
#define KC 16
#define BS_LD 68

#define SM_AS   0
#define SM_BS   (C_DIM * TN)
#define SM_REDV (SM_BS + KC * BS_LD)
#define SM_REDI (SM_REDV + 16 * TN)
#define SM_TOTAL_FLOATS (SM_REDI + 16 * TN)

__global__ void __launch_bounds__(256, 2) k_argmin(
        const float* __restrict__ z,
        const float* __restrict__ cb,
        float* __restrict__ out)
{
    extern __shared__ float smem[];
    float* As   = smem + SM_AS;
    float* Bs   = smem + SM_BS;
    float* redv = smem + SM_REDV;
    int*   redi = (int*)(smem + SM_REDI);

    const int tid = threadIdx.x;
    const int nb  = blockIdx.x;              // 512 blocks
    const int b   = nb >> 6;
    const int h   = nb & 63;
    const float* zbase = z + ((long)b * 1048576 + h * 64);  // + c*4096 + w

    // Load z tile (coalesced: fixed w = tid&63)
    {
        const int w  = tid & 63;
        const int c0 = tid >> 6;
        #pragma unroll 8
        for (int p = 0; p < 64; ++p) {
            int c = c0 + (p << 2);
            As[c * TN + w] = zbase[(long)c * 4096 + w];
        }
    }
    __syncthreads();

    const int tx = tid & 15, ty = tid >> 4;
    const int n0 = tx * 4;

    // A_n for this thread's 4 n values (exact reference values)
    float An[4];
    #pragma unroll
    for (int i = 0; i < 4; ++i) An[i] = g_rowA[nb * TN + n0 + i];

    float bestd[4]; int besti[4];
    #pragma unroll
    for (int i = 0; i < 4; ++i) { bestd[i] = CUDART_INF_F; besti[i] = 0; }

    for (int et = 0; et < N_EMB / TE; ++et) {
        const int e0 = et * TE;
        float acc[4][4];
        #pragma unroll
        for (int j = 0; j < 4; ++j)
            #pragma unroll
            for (int i = 0; i < 4; ++i) acc[j][i] = 0.f;

        for (int kc = 0; kc < C_DIM; kc += KC) {
            __syncthreads();
            #pragma unroll
            for (int q = 0; q < 4; ++q) {
                int i2 = q * 256 + tid;
                int e = i2 >> 4, k = i2 & 15;
                Bs[k * BS_LD + e] = cb[(e0 + e) * C_DIM + kc + k];
            }
            __syncthreads();
            #pragma unroll
            for (int k = 0; k < KC; ++k) {      // k strictly ascending overall
                float4 a = *(const float4*)&As[(kc + k) * TN + n0];
                float4 bq = *(const float4*)&Bs[k * BS_LD + ty * 4];
                float bj[4] = {bq.x, bq.y, bq.z, bq.w};
                #pragma unroll
                for (int j = 0; j < 4; ++j) {
                    acc[j][0] = fmaf(bj[j], a.x, acc[j][0]);
                    acc[j][1] = fmaf(bj[j], a.y, acc[j][1]);
                    acc[j][2] = fmaf(bj[j], a.z, acc[j][2]);
                    acc[j][3] = fmaf(bj[j], a.w, acc[j][3]);
                }
            }
        }

        // d = fl( fl(A+B) - fl(2*M) ); running argmin, e ascending, strict <
        #pragma unroll
        for (int j = 0; j < 4; ++j) {
            int e = e0 + ty * 4 + j;
            float Be = g_e2[e];
            #pragma unroll
            for (int i = 0; i < 4; ++i) {
                float t = __fadd_rn(An[i], Be);
                float d = __fsub_rn(t, __fmul_rn(2.0f, acc[j][i]));
                if (d < bestd[i]) { bestd[i] = d; besti[i] = e; }
            }
        }
    }

    __syncthreads();
    #pragma unroll
    for (int i = 0; i < 4; ++i) {
        redv[ty * TN + n0 + i] = bestd[i];
        redi[ty * TN + n0 + i] = besti[i];
    }
    __syncthreads();

    if (tid < TN) {
        const int n = tid;
        float bv = redv[n]; int bi = redi[n];
        #pragma unroll
        for (int t = 1; t < 16; ++t) {
            float v = redv[t * TN + n]; int ii = redi[t * TN + n];
            if (v < bv || (v == bv && ii < bi)) { bv = v; bi = ii; }
        }
        const int gn = nb * TN + n;
        g_idx[gn] = bi;
        out[IDX_OFF + gn] = (float)bi;

        float dmin = bv;   // quantized d_min == ||z-e*||^2 within 4.6e-5
        #pragma unroll
        for (int o = 16; o; o >>= 1) dmin += __shfl_xor_sync(0xFFFFFFFFu, dmin, o);
        if ((tid & 31) == 0) atomicAdd(&g_loss_sum, (double)dmin);
    }
}

// ---------------------------------------------------------------------------
// k_scatter: z_q_out[b,c,h,w] = codebook[idx[n], c]; coalesced writes.
// ---------------------------------------------------------------------------
__global__ void k_scatter(const float* __restrict__ cb, float* __restrict__ out) {
    long gid = (long)blockIdx.x * 256 + threadIdx.x;     // 0 .. 8388607
    int hw = (int)(gid & 4095);
    int c  = (int)((gid >> 12) & 255);
    int b  = (int)(gid >> 20);
    int n  = (b << 12) | hw;
    int id = g_idx[n];
    out[gid] = __ldg(&cb[id * C_DIM + c]);
}

__global__ void k_loss(float* __restrict__ out) {
    out[LOSS_OFF] = (float)(1.25 * g_loss_sum / (double)Z_ELEMS);
}

// ---------------------------------------------------------------------------
extern "C" void kernel_launch(void* const* d_in, const int* in_sizes, int n_in,
                              void* d_out, int out_size) {
    const float* z  = (const float*)d_in[0];
    const float* cb = (const float*)d_in[1];
    if (n_in >= 2 && in_sizes[0] == N_EMB * C_DIM && in_sizes[1] == Z_ELEMS) {
        z  = (const float*)d_in[1];
        cb = (const float*)d_in[0];
    }
    float* out = (float*)d_out;

    static const int smem_bytes = SM_TOTAL_FLOATS * 4;
    cudaFuncSetAttribute(k_argmin, cudaFuncAttributeMaxDynamicSharedMemorySize,
                         smem_bytes);

    k_prep<<<N_EMB / 256, 256>>>(cb);
    k_rowA<<<N_VEC / 256, 256>>>(z);
    k_argmin<<<N_VEC / TN, 256, smem_bytes>>>(z, cb, out);
    k_scatter<<<Z_ELEMS / 256, 256>>>(cb, out);
    k_loss<<<1, 1>>>(out);
}